// round 16
// baseline (speedup 1.0000x reference)
#include <cuda_runtime.h>
#include <cuda_fp16.h>
#include <math.h>
#include <stdint.h>

#define N_TOK 2048
#define D_IN  1024
#define NH    16
#define E     64

// ===========================================================================
// Device scratch. Q/K split fp16 hi/lo; V, ctx hi-only. Vt transposed.
// ===========================================================================
__device__ __half g_Qh[NH * N_TOK * E];
__device__ __half g_Ql[NH * N_TOK * E];
__device__ __half g_Kh[NH * N_TOK * E];
__device__ __half g_Kl[NH * N_TOK * E];
__device__ __half g_Vth[NH * E * N_TOK];   // [h][e][n], hi only

__device__ __half g_xh[N_TOK * D_IN];
__device__ __half g_xl[N_TOK * D_IN];
__device__ __half g_Wth[2048 * D_IN];   // [n][k], Q|K only
__device__ __half g_Wtl[2048 * D_IN];
__device__ __half g_Wvh[1024 * D_IN];   // V weights [n][k]
__device__ __half g_Wvl[1024 * D_IN];
__device__ __half g_Woth[D_IN * D_IN];  // [n][k] = Wo[k][n], hi only
__device__ __half g_ctxh[N_TOK * D_IN];

__device__ __forceinline__ void split_store(float v, __half* hi, __half* lo) {
    __half h = __float2half_rn(v);
    *hi = h;
    *lo = __float2half_rn(v - __half2float(h));
}

__device__ __forceinline__ uint32_t smem_u32(const void* p) {
    uint32_t a;
    asm("{ .reg .u64 t; cvta.to.shared.u64 t, %1; cvt.u32.u64 %0, t; }" : "=r"(a) : "l"(p));
    return a;
}
__device__ __forceinline__ void cp16(uint32_t dst, const void* src) {
    asm volatile("cp.async.cg.shared.global [%0], [%1], 16;" :: "r"(dst), "l"(src) : "memory");
}
#define CP_COMMIT() asm volatile("cp.async.commit_group;" ::: "memory")
#define CP_WAIT0()  asm volatile("cp.async.wait_group 0;" ::: "memory")
#define CP_WAIT1()  asm volatile("cp.async.wait_group 1;" ::: "memory")

__device__ __forceinline__ void mma_f(float* d, const uint32_t* a, const uint32_t* b) {
    asm volatile(
        "mma.sync.aligned.m16n8k16.row.col.f32.f16.f16.f32 "
        "{%0,%1,%2,%3}, {%4,%5,%6,%7}, {%8,%9}, {%0,%1,%2,%3};"
        : "+f"(d[0]), "+f"(d[1]), "+f"(d[2]), "+f"(d[3])
        : "r"(a[0]), "r"(a[1]), "r"(a[2]), "r"(a[3]), "r"(b[0]), "r"(b[1]));
}

__device__ __forceinline__ void ldsm_x4(uint32_t* r, uint32_t addr) {
    asm volatile("ldmatrix.sync.aligned.m8n8.x4.shared.b16 {%0,%1,%2,%3}, [%4];"
                 : "=r"(r[0]), "=r"(r[1]), "=r"(r[2]), "=r"(r[3]) : "r"(addr));
}

__device__ __forceinline__ uint32_t pack_h2(float p0, float p1) {
    __half2 h = __floats2half2_rn(p0, p1);
    return *(uint32_t*)&h;
}
__device__ __forceinline__ void split_pack(float p0, float p1, uint32_t& wh, uint32_t& wl) {
    wh = pack_h2(p0, p1);
    float2 f = __half22float2(*(__half2*)&wh);
    wl = pack_h2(p0 - f.x, p1 - f.y);
}

// e^x on the FFMA pipe
__device__ __forceinline__ float fast_exp(float x) {
    x = fmaxf(x, -80.f);
    float t = fmaf(x, 1.4426950408889634f, 12582912.f);
    int   i = __float_as_int(t);
    float r = t - 12582912.f;
    float f = fmaf(x, 1.4426950408889634f, -r);
    float p = 1.3333558e-3f;
    p = fmaf(p, f, 9.6181291e-3f);
    p = fmaf(p, f, 5.5504109e-2f);
    p = fmaf(p, f, 2.4022651e-1f);
    p = fmaf(p, f, 6.9314718e-1f);
    p = fmaf(p, f, 1.0f);
    return __int_as_float(__float_as_int(p) + (i << 23));
}

// ===========================================================================
// Prep kernels
// ===========================================================================
__global__ __launch_bounds__(256) void split_x_kernel(const float* __restrict__ x)
{
    int i0 = (blockIdx.x * 256 + threadIdx.x) * 4;
    float4 v = *(const float4*)(x + i0);
    split_store(v.x, &g_xh[i0 + 0], &g_xl[i0 + 0]);
    split_store(v.y, &g_xh[i0 + 1], &g_xl[i0 + 1]);
    split_store(v.z, &g_xh[i0 + 2], &g_xl[i0 + 2]);
    split_store(v.w, &g_xh[i0 + 3], &g_xl[i0 + 3]);
}

// Fused weight conversion: z<3 -> Wq/Wk/Wv, z==3 -> Wo.
__global__ __launch_bounds__(256) void conv_all_kernel(
    const float* __restrict__ Wq, const float* __restrict__ Wk,
    const float* __restrict__ Wv, const float* __restrict__ Wo)
{
    __shared__ float t[64][65];
    const int tid = threadIdx.x;
    const int sel = blockIdx.z;

    if (sel < 3) {
        const int d0 = blockIdx.x * 64, h = blockIdx.y;
        const float* W = (sel == 0 ? Wq : (sel == 1 ? Wk : Wv)) + (size_t)h * (D_IN * E);
        #pragma unroll
        for (int i = 0; i < 16; i++) {
            int idx = i * 256 + tid, r = idx >> 6, e = idx & 63;
            t[r][e] = W[(size_t)(d0 + r) * E + e];
        }
        __syncthreads();
        const int nb = h * 64;
        #pragma unroll
        for (int i = 0; i < 16; i++) {
            int idx = i * 256 + tid, er = idx >> 6, d = idx & 63;
            float v = t[d][er];
            if (sel < 2) {
                size_t o = (size_t)(sel * 1024 + nb + er) * D_IN + d0 + d;
                split_store(v, &g_Wth[o], &g_Wtl[o]);
            } else {
                size_t o = (size_t)(nb + er) * D_IN + d0 + d;
                split_store(v, &g_Wvh[o], &g_Wvl[o]);
            }
        }
    } else {
        const int k0 = blockIdx.x * 64, n0 = blockIdx.y * 64;
        #pragma unroll
        for (int i = 0; i < 16; i++) {
            int idx = i * 256 + tid, r = idx >> 6, c = idx & 63;
            t[r][c] = Wo[(size_t)(k0 + r) * D_IN + n0 + c];
        }
        __syncthreads();
        #pragma unroll
        for (int i = 0; i < 16; i++) {
            int idx = i * 256 + tid, nr = idx >> 6, k = idx & 63;
            g_Woth[(size_t)(n0 + nr) * D_IN + k0 + k] = __float2half_rn(t[k][nr]);
        }
    }
}

// ===========================================================================
// Fused QKV GEMM. blockIdx.x < 16: QK 3-term (BN=128). >=16: V 2-term (BN=64).
// ===========================================================================
#define TSTRB 80
#define ATILE_B (128 * TSTRB)            // 10240
#define QKV_SMEM (2 * (2 * ATILE_B + 2 * 128 * TSTRB))    // 81920 (QK path size)

__global__ __launch_bounds__(256, 2) void gemm_qkv_kernel(
    const __half* __restrict__ Ah, const __half* __restrict__ Al,
    const __half* __restrict__ Bh, const __half* __restrict__ Bl,
    const __half* __restrict__ Vh, const __half* __restrict__ Vl)
{
    extern __shared__ __align__(16) char smem[];
    const int tid  = threadIdx.x;
    const int wid  = tid >> 5, lane = tid & 31;
    const int grp  = lane >> 2, qid = lane & 3;
    const int m0   = blockIdx.y * 128;
    const int wm   = (wid >> 1) * 32;
    const uint32_t smb = smem_u32(smem);

    const int arow  = ((lane >> 3) & 1) * 8 + (lane & 7);
    const int acol  = ((lane >> 4) & 1) * 16;
    const int brow  = ((lane >> 4) & 1) * 8 + (lane & 7);
    const int bcol  = ((lane >> 3) & 1) * 16;
    const int NC = D_IN / 32;

    if (blockIdx.x < 16) {
        // ---------------- QK path: 3-term, BN=128 ----------------
        constexpr int BN = 128;
        constexpr int BTILE_B = BN * TSTRB;
        constexpr int BUF_B   = 2 * ATILE_B + 2 * BTILE_B;
        constexpr int NP      = BN / 32;
        const int n0 = blockIdx.x * BN;
        const int wn = (wid & 1) * (BN / 2);

        float acc[2][2 * NP][4] = {};

        auto load_tiles = [&](int buf, int kc) {
            const uint32_t bb = smb + buf * BUF_B;
            #pragma unroll
            for (int i = 0; i < 4; i++) {
                int c = i * 256 + tid;
                int t = c >> 9, w = c & 511, row = w >> 2, ch = w & 3;
                const __half* S = (t ? Al : Ah);
                cp16(bb + t * ATILE_B + row * TSTRB + ch * 16,
                     S + (size_t)(m0 + row) * D_IN + kc * 32 + ch * 8);
            }
            #pragma unroll
            for (int i = 0; i < 4; i++) {
                int c = i * 256 + tid;
                int t = c >> 9, w = c & 511, row = w >> 2, ch = w & 3;
                const __half* S = (t ? Bl : Bh);
                cp16(bb + 2 * ATILE_B + t * BTILE_B + row * TSTRB + ch * 16,
                     S + (size_t)(n0 + row) * D_IN + kc * 32 + ch * 8);
            }
        };

        load_tiles(0, 0);
        CP_COMMIT();

        #pragma unroll 1
        for (int kc = 0; kc < NC; kc++) {
            const int cur = kc & 1;
            if (kc + 1 < NC) {
                load_tiles(1 - cur, kc + 1);
                CP_COMMIT();
                CP_WAIT1();
            } else {
                CP_WAIT0();
            }
            __syncthreads();

            const uint32_t Ah_b = smb + cur * BUF_B;
            const uint32_t Al_b = Ah_b + ATILE_B;
            const uint32_t Bh_b = Ah_b + 2 * ATILE_B;
            const uint32_t Bl_b = Bh_b + BTILE_B;

            #pragma unroll
            for (int k16 = 0; k16 < 2; k16++) {
                const int cb = k16 * 32 + acol;
                uint32_t ah0[4], ah1[4], al0[4], al1[4];
                ldsm_x4(ah0, Ah_b + (wm + arow) * TSTRB + cb);
                ldsm_x4(ah1, Ah_b + (wm + 16 + arow) * TSTRB + cb);
                ldsm_x4(al0, Al_b + (wm + arow) * TSTRB + cb);
                ldsm_x4(al1, Al_b + (wm + 16 + arow) * TSTRB + cb);
                const int cbb = k16 * 32 + bcol;
                #pragma unroll
                for (int np = 0; np < NP; np++) {
                    uint32_t bh[4], bl[4];
                    ldsm_x4(bh, Bh_b + (wn + np * 16 + brow) * TSTRB + cbb);
                    ldsm_x4(bl, Bl_b + (wn + np * 16 + brow) * TSTRB + cbb);
                    mma_f(acc[0][2*np],   ah0, bh);
                    mma_f(acc[0][2*np+1], ah0, bh + 2);
                    mma_f(acc[1][2*np],   ah1, bh);
                    mma_f(acc[1][2*np+1], ah1, bh + 2);
                    mma_f(acc[0][2*np],   ah0, bl);
                    mma_f(acc[0][2*np+1], ah0, bl + 2);
                    mma_f(acc[1][2*np],   ah1, bl);
                    mma_f(acc[1][2*np+1], ah1, bl + 2);
                    mma_f(acc[0][2*np],   al0, bh);
                    mma_f(acc[0][2*np+1], al0, bh + 2);
                    mma_f(acc[1][2*np],   al1, bh);
                    mma_f(acc[1][2*np+1], al1, bh + 2);
                }
            }
            __syncthreads();
        }

        #pragma unroll
        for (int mt = 0; mt < 2; mt++) {
            #pragma unroll
            for (int nt = 0; nt < 2 * NP; nt++) {
                int n = n0 + wn + nt * 8 + qid * 2;
                #pragma unroll
                for (int half = 0; half < 2; half++) {
                    int m = m0 + wm + mt * 16 + grp + half * 8;
                    float v0 = acc[mt][nt][half * 2], v1 = acc[mt][nt][half * 2 + 1];
                    int sel = n >> 10, w = n & 1023, h = w >> 6, e = w & 63;
                    __half* bh = (sel == 0 ? g_Qh : g_Kh);
                    __half* bl = (sel == 0 ? g_Ql : g_Kl);
                    size_t o = ((size_t)h * N_TOK + m) * E + e;
                    uint32_t wh, wl;
                    split_pack(v0, v1, wh, wl);
                    *(uint32_t*)(bh + o) = wh;
                    *(uint32_t*)(bl + o) = wl;
                }
            }
        }
    } else {
        // ---------------- V path: 2-term, BN=64 ----------------
        constexpr int BN = 64;
        constexpr int BTILE_B = BN * TSTRB;
        constexpr int BUF_B   = ATILE_B + 2 * BTILE_B;
        constexpr int NP      = BN / 32;
        const int n0 = (blockIdx.x - 16) * BN;
        const int wn = (wid & 1) * (BN / 2);

        float acc[2][2 * NP][4] = {};

        auto load_tiles = [&](int buf, int kc) {
            const uint32_t bb = smb + buf * BUF_B;
            #pragma unroll
            for (int i = 0; i < 2; i++) {
                int c = i * 256 + tid;
                int row = c >> 2, ch = c & 3;
                cp16(bb + row * TSTRB + ch * 16,
                     Ah + (size_t)(m0 + row) * D_IN + kc * 32 + ch * 8);
            }
            #pragma unroll
            for (int i = 0; i < 2; i++) {
                int c = i * 256 + tid;
                int t = c >> 8, w = c & 255, row = w >> 2, ch = w & 3;
                const __half* S = (t ? Vl : Vh);
                cp16(bb + ATILE_B + t * BTILE_B + row * TSTRB + ch * 16,
                     S + (size_t)(n0 + row) * D_IN + kc * 32 + ch * 8);
            }
        };

        load_tiles(0, 0);
        CP_COMMIT();

        #pragma unroll 1
        for (int kc = 0; kc < NC; kc++) {
            const int cur = kc & 1;
            if (kc + 1 < NC) {
                load_tiles(1 - cur, kc + 1);
                CP_COMMIT();
                CP_WAIT1();
            } else {
                CP_WAIT0();
            }
            __syncthreads();

            const uint32_t A_b  = smb + cur * BUF_B;
            const uint32_t Bh_b = A_b + ATILE_B;
            const uint32_t Bl_b = Bh_b + BTILE_B;

            #pragma unroll
            for (int k16 = 0; k16 < 2; k16++) {
                const int cb = k16 * 32 + acol;
                uint32_t a0[4], a1[4];
                ldsm_x4(a0, A_b + (wm + arow) * TSTRB + cb);
                ldsm_x4(a1, A_b + (wm + 16 + arow) * TSTRB + cb);
                const int cbb = k16 * 32 + bcol;
                #pragma unroll
                for (int np = 0; np < NP; np++) {
                    uint32_t bh[4], bl[4];
                    ldsm_x4(bh, Bh_b + (wn + np * 16 + brow) * TSTRB + cbb);
                    ldsm_x4(bl, Bl_b + (wn + np * 16 + brow) * TSTRB + cbb);
                    mma_f(acc[0][2*np],   a0, bh);
                    mma_f(acc[0][2*np+1], a0, bh + 2);
                    mma_f(acc[1][2*np],   a1, bh);
                    mma_f(acc[1][2*np+1], a1, bh + 2);
                    mma_f(acc[0][2*np],   a0, bl);
                    mma_f(acc[0][2*np+1], a0, bl + 2);
                    mma_f(acc[1][2*np],   a1, bl);
                    mma_f(acc[1][2*np+1], a1, bl + 2);
                }
            }
            __syncthreads();
        }

        #pragma unroll
        for (int mt = 0; mt < 2; mt++) {
            #pragma unroll
            for (int nt = 0; nt < 2 * NP; nt++) {
                int n = n0 + wn + nt * 8 + qid * 2;
                int h = n >> 6, e = n & 63;
                #pragma unroll
                for (int half = 0; half < 2; half++) {
                    int m = m0 + wm + mt * 16 + grp + half * 8;
                    size_t o = ((size_t)h * E + e) * N_TOK + m;
                    g_Vth[o]         = __float2half_rn(acc[mt][nt][half * 2]);
                    g_Vth[o + N_TOK] = __float2half_rn(acc[mt][nt][half * 2 + 1]);
                }
            }
        }
    }
}

// ===========================================================================
// 1-term GEMM (outproj): out = ctx_h @ Wo_h^T, fp32 out. BN=64.
// ===========================================================================
__global__ __launch_bounds__(256, 2) void gemm1_kernel(
    const __half* __restrict__ Ah, const __half* __restrict__ Bh,
    float* __restrict__ outp)
{
    constexpr int BN = 64;
    constexpr int BTILE_B = BN * TSTRB;
    constexpr int BUF_B   = ATILE_B + BTILE_B;
    constexpr int NP      = BN / 32;
    extern __shared__ __align__(16) char smem[];
    const int tid  = threadIdx.x;
    const int wid  = tid >> 5, lane = tid & 31;
    const int grp  = lane >> 2, qid = lane & 3;
    const int n0   = blockIdx.x * BN, m0 = blockIdx.y * 128;
    const int wm   = (wid >> 1) * 32;
    const int wn   = (wid & 1) * (BN / 2);

    const uint32_t smb = smem_u32(smem);

    const int arow  = ((lane >> 3) & 1) * 8 + (lane & 7);
    const int acol  = ((lane >> 4) & 1) * 16;
    const int brow  = ((lane >> 4) & 1) * 8 + (lane & 7);
    const int bcol  = ((lane >> 3) & 1) * 16;

    float acc[2][2 * NP][4] = {};

    auto load_tiles = [&](int buf, int kc) {
        const uint32_t bb = smb + buf * BUF_B;
        #pragma unroll
        for (int i = 0; i < 2; i++) {
            int c = i * 256 + tid;
            int row = c >> 2, ch = c & 3;
            cp16(bb + row * TSTRB + ch * 16,
                 Ah + (size_t)(m0 + row) * D_IN + kc * 32 + ch * 8);
        }
        {
            int c = tid;
            int row = c >> 2, ch = c & 3;
            cp16(bb + ATILE_B + row * TSTRB + ch * 16,
                 Bh + (size_t)(n0 + row) * D_IN + kc * 32 + ch * 8);
        }
    };

    load_tiles(0, 0);
    CP_COMMIT();

    const int NC = D_IN / 32;
    #pragma unroll 1
    for (int kc = 0; kc < NC; kc++) {
        const int cur = kc & 1;
        if (kc + 1 < NC) {
            load_tiles(1 - cur, kc + 1);
            CP_COMMIT();
            CP_WAIT1();
        } else {
            CP_WAIT0();
        }
        __syncthreads();

        const uint32_t A_b  = smb + cur * BUF_B;
        const uint32_t Bh_b = A_b + ATILE_B;

        #pragma unroll
        for (int k16 = 0; k16 < 2; k16++) {
            const int cb = k16 * 32 + acol;
            uint32_t a0[4], a1[4];
            ldsm_x4(a0, A_b + (wm + arow) * TSTRB + cb);
            ldsm_x4(a1, A_b + (wm + 16 + arow) * TSTRB + cb);
            const int cbb = k16 * 32 + bcol;
            #pragma unroll
            for (int np = 0; np < NP; np++) {
                uint32_t bh[4];
                ldsm_x4(bh, Bh_b + (wn + np * 16 + brow) * TSTRB + cbb);
                mma_f(acc[0][2*np],   a0, bh);
                mma_f(acc[0][2*np+1], a0, bh + 2);
                mma_f(acc[1][2*np],   a1, bh);
                mma_f(acc[1][2*np+1], a1, bh + 2);
            }
        }
        __syncthreads();
    }

    #pragma unroll
    for (int mt = 0; mt < 2; mt++) {
        #pragma unroll
        for (int nt = 0; nt < 2 * NP; nt++) {
            int n = n0 + wn + nt * 8 + qid * 2;
            #pragma unroll
            for (int half = 0; half < 2; half++) {
                int m = m0 + wm + mt * 16 + grp + half * 8;
                *(float2*)(outp + (size_t)m * D_IN + n) =
                    make_float2(acc[mt][nt][half * 2], acc[mt][nt][half * 2 + 1]);
            }
        }
    }
}
#define GEMM1_SMEM (2 * (ATILE_B + 64 * TSTRB))           // 30720

// ===========================================================================
// HMMA flash attention. S: 3-term. PV: 1-term. ctx hi-only.
// ===========================================================================
#define BQ 128
#define BK 64
#define KSTR 144
#define VSTR 144
#define QBUF  (128 * KSTR)
#define OFF_Q   0
#define KBUF  (BK * KSTR)
#define OFF_K0  (2 * QBUF)
#define OFF_K1  (OFF_K0 + 2 * KBUF)
#define VBUF  (E * VSTR)
#define OFF_VT0 (OFF_K1 + 2 * KBUF)
#define OFF_VT1 (OFF_VT0 + VBUF)
#define ATTN_SMEM (OFF_VT1 + VBUF)           // 92160

__global__ __launch_bounds__(256, 2) void attn_kernel()
{
    extern __shared__ __align__(16) char smem[];
    const uint32_t smb = smem_u32(smem);
    const int tid = threadIdx.x, wid = tid >> 5, lane = tid & 31;
    const int grp = lane >> 2, qid = lane & 3;
    const int h = blockIdx.y;
    const int q0 = blockIdx.x * BQ;
    const int wm = wid * 16;

    const __half* gQh = g_Qh + ((size_t)h * N_TOK + q0) * E;
    const __half* gQl = g_Ql + ((size_t)h * N_TOK + q0) * E;
    const __half* gKh = g_Kh + (size_t)h * N_TOK * E;
    const __half* gKl = g_Kl + (size_t)h * N_TOK * E;
    const __half* gVth = g_Vth + (size_t)h * E * N_TOK;

    const int arow = ((lane >> 3) & 1) * 8 + (lane & 7);
    const int acol = ((lane >> 4) & 1) * 16;
    const int brow = ((lane >> 4) & 1) * 8 + (lane & 7);
    const int bcol = ((lane >> 3) & 1) * 16;

    auto load_kv = [&](uint32_t koff, uint32_t voff, int c) {
        #pragma unroll
        for (int i = 0; i < 4; i++) {
            int idx = i * 256 + tid;
            int t = idx >> 9, w = idx & 511, row = w >> 3, ch = w & 7;
            const __half* S = (t ? gKl : gKh);
            cp16(smb + koff + t * KBUF + row * KSTR + ch * 16,
                 S + ((size_t)c * BK + row) * E + ch * 8);
        }
        #pragma unroll
        for (int i = 0; i < 2; i++) {
            int idx = i * 256 + tid;
            int row = idx >> 3, ch = idx & 7;
            cp16(smb + voff + row * VSTR + ch * 16,
                 gVth + (size_t)row * N_TOK + c * BK + ch * 8);
        }
    };

    #pragma unroll
    for (int i = 0; i < 4; i++) {
        int idx = i * 256 + tid;
        int row = idx >> 3, ch = idx & 7;
        uint32_t so = row * KSTR + ch * 16;
        size_t  go = (size_t)row * E + ch * 8;
        cp16(smb + OFF_Q + so,        gQh + go);
        cp16(smb + OFF_Q + QBUF + so, gQl + go);
    }
    load_kv(OFF_K0, OFF_VT0, 0);
    CP_COMMIT();

    float accO[8][4] = {};
    float m0 = -1e30f, m1 = -1e30f, l0 = 0.f, l1 = 0.f;

    CP_WAIT0();
    __syncthreads();

    for (int c = 0; c < N_TOK / BK; c++) {
        const uint32_t kb  = smb + ((c & 1) ? OFF_K1 : OFF_K0);
        const uint32_t vtb = smb + ((c & 1) ? OFF_VT1 : OFF_VT0);

        float accS[8][4] = {};
        #pragma unroll
        for (int k16 = 0; k16 < 4; k16++) {
            uint32_t ah[4], al[4];
            const uint32_t aaddr = smb + OFF_Q + (wm + arow) * KSTR + k16 * 32 + acol;
            ldsm_x4(ah, aaddr);
            ldsm_x4(al, aaddr + QBUF);
            #pragma unroll
            for (int np = 0; np < 4; np++) {
                uint32_t bh[4], bl[4];
                const uint32_t baddr = kb + (np * 16 + brow) * KSTR + k16 * 32 + bcol;
                ldsm_x4(bh, baddr);
                ldsm_x4(bl, baddr + KBUF);
                mma_f(accS[2*np],   ah, bh);
                mma_f(accS[2*np+1], ah, bh + 2);
                mma_f(accS[2*np],   ah, bl);
                mma_f(accS[2*np+1], ah, bl + 2);
                mma_f(accS[2*np],   al, bh);
                mma_f(accS[2*np+1], al, bh + 2);
            }
        }

        if (c + 1 < N_TOK / BK) {
            load_kv((c & 1) ? OFF_K0 : OFF_K1, (c & 1) ? OFF_VT0 : OFF_VT1, c + 1);
            CP_COMMIT();
        }

        float mx0 = -1e30f, mx1 = -1e30f;
        #pragma unroll
        for (int n8 = 0; n8 < 8; n8++) {
            mx0 = fmaxf(mx0, fmaxf(accS[n8][0], accS[n8][1]));
            mx1 = fmaxf(mx1, fmaxf(accS[n8][2], accS[n8][3]));
        }
        mx0 = fmaxf(mx0, __shfl_xor_sync(0xffffffff, mx0, 1));
        mx0 = fmaxf(mx0, __shfl_xor_sync(0xffffffff, mx0, 2));
        mx1 = fmaxf(mx1, __shfl_xor_sync(0xffffffff, mx1, 1));
        mx1 = fmaxf(mx1, __shfl_xor_sync(0xffffffff, mx1, 2));
        float mn0 = fmaxf(m0, mx0), mn1 = fmaxf(m1, mx1);
        float al0 = fast_exp((m0 - mn0) * 0.125f);
        float al1 = fast_exp((m1 - mn1) * 0.125f);
        m0 = mn0; m1 = mn1;
        float s0 = 0.f, s1 = 0.f;
        #pragma unroll
        for (int n8 = 0; n8 < 8; n8++) {
            accS[n8][0] = fast_exp((accS[n8][0] - m0) * 0.125f);
            accS[n8][1] = fast_exp((accS[n8][1] - m0) * 0.125f);
            accS[n8][2] = fast_exp((accS[n8][2] - m1) * 0.125f);
            accS[n8][3] = fast_exp((accS[n8][3] - m1) * 0.125f);
            s0 += accS[n8][0] + accS[n8][1];
            s1 += accS[n8][2] + accS[n8][3];
        }
        s0 += __shfl_xor_sync(0xffffffff, s0, 1);
        s0 += __shfl_xor_sync(0xffffffff, s0, 2);
        s1 += __shfl_xor_sync(0xffffffff, s1, 1);
        s1 += __shfl_xor_sync(0xffffffff, s1, 2);
        l0 = l0 * al0 + s0;
        l1 = l1 * al1 + s1;
        #pragma unroll
        for (int n8v = 0; n8v < 8; n8v++) {
            accO[n8v][0] *= al0; accO[n8v][1] *= al0;
            accO[n8v][2] *= al1; accO[n8v][3] *= al1;
        }

        #pragma unroll
        for (int kk = 0; kk < 4; kk++) {
            uint32_t ph[4];
            ph[0] = pack_h2(accS[2 * kk][0],     accS[2 * kk][1]);
            ph[1] = pack_h2(accS[2 * kk][2],     accS[2 * kk][3]);
            ph[2] = pack_h2(accS[2 * kk + 1][0], accS[2 * kk + 1][1]);
            ph[3] = pack_h2(accS[2 * kk + 1][2], accS[2 * kk + 1][3]);
            #pragma unroll
            for (int np = 0; np < 4; np++) {
                uint32_t bh[4];
                ldsm_x4(bh, vtb + (np * 16 + brow) * VSTR + kk * 32 + bcol);
                mma_f(accO[2*np],   ph, bh);
                mma_f(accO[2*np+1], ph, bh + 2);
            }
        }

        if (c + 1 < N_TOK / BK) {
            CP_WAIT0();
            __syncthreads();
        }
    }

    float inv0 = 1.f / l0, inv1 = 1.f / l1;
    const int row0 = q0 + wm + grp, row1 = row0 + 8;
    #pragma unroll
    for (int n8v = 0; n8v < 8; n8v++) {
        int colb = h * E + n8v * 8 + qid * 2;
        *(uint32_t*)(g_ctxh + (size_t)row0 * D_IN + colb) =
            pack_h2(accO[n8v][0] * inv0, accO[n8v][1] * inv0);
        *(uint32_t*)(g_ctxh + (size_t)row1 * D_IN + colb) =
            pack_h2(accO[n8v][2] * inv1, accO[n8v][3] * inv1);
    }
}

// ===========================================================================
extern "C" void kernel_launch(void* const* d_in, const int* in_sizes, int n_in,
                              void* d_out, int out_size)
{
    const float* x  = (const float*)d_in[0];
    const float* Wq = (const float*)d_in[1];
    const float* Wk = (const float*)d_in[2];
    const float* Wv = (const float*)d_in[3];
    const float* Wo = (const float*)d_in[4];
    float* out = (float*)d_out;
    (void)in_sizes; (void)n_in; (void)out_size;

    cudaFuncSetAttribute(attn_kernel,
                         cudaFuncAttributeMaxDynamicSharedMemorySize, ATTN_SMEM);
    cudaFuncSetAttribute(gemm_qkv_kernel,
                         cudaFuncAttributeMaxDynamicSharedMemorySize, QKV_SMEM);
    cudaFuncSetAttribute(gemm1_kernel,
                         cudaFuncAttributeMaxDynamicSharedMemorySize, GEMM1_SMEM);

    static __half *p_xh = nullptr, *p_xl, *p_Wth, *p_Wtl, *p_Wvh, *p_Wvl, *p_Woth, *p_ch;
    if (!p_xh) {
        cudaGetSymbolAddress((void**)&p_xh,  g_xh);
        cudaGetSymbolAddress((void**)&p_xl,  g_xl);
        cudaGetSymbolAddress((void**)&p_Wth, g_Wth);
        cudaGetSymbolAddress((void**)&p_Wtl, g_Wtl);
        cudaGetSymbolAddress((void**)&p_Wvh, g_Wvh);
        cudaGetSymbolAddress((void**)&p_Wvl, g_Wvl);
        cudaGetSymbolAddress((void**)&p_Woth, g_Woth);
        cudaGetSymbolAddress((void**)&p_ch,  g_ctxh);
    }

    // prep (2 launches)
    split_x_kernel<<<(N_TOK * D_IN) / (256 * 4), 256>>>(x);
    dim3 gc(D_IN / 64, 16, 4);
    conv_all_kernel<<<gc, 256>>>(Wq, Wk, Wv, Wo);

    // fused QK(3-term) + V(2-term) GEMM: grid (16+16) x 16
    dim3 g1(32, N_TOK / 128);
    gemm_qkv_kernel<<<g1, 256, QKV_SMEM>>>(p_xh, p_xl, p_Wth, p_Wtl, p_Wvh, p_Wvl);

    // HMMA flash attention
    dim3 g2(N_TOK / BQ, NH);
    attn_kernel<<<g2, 256, ATTN_SMEM>>>();

    // outproj 1-term (BN=64: grid 16 x 16)
    dim3 g3(D_IN / 64, N_TOK / 128);
    gemm1_kernel<<<g3, 256, GEMM1_SMEM>>>(p_ch, p_Woth, out);
}

// round 17
// speedup vs baseline: 1.0775x; 1.0775x over previous
#include <cuda_runtime.h>
#include <cuda_fp16.h>
#include <math.h>
#include <stdint.h>

#define N_TOK 2048
#define D_IN  1024
#define NH    16
#define E     64

// ===========================================================================
// Device scratch. Q/K split fp16 hi/lo; V, ctx hi-only. Vt transposed.
// ===========================================================================
__device__ __half g_Qh[NH * N_TOK * E];
__device__ __half g_Ql[NH * N_TOK * E];
__device__ __half g_Kh[NH * N_TOK * E];
__device__ __half g_Kl[NH * N_TOK * E];
__device__ __half g_Vth[NH * E * N_TOK];   // [h][e][n], hi only

__device__ __half g_xh[N_TOK * D_IN];
__device__ __half g_xl[N_TOK * D_IN];
__device__ __half g_Wth[2048 * D_IN];   // [n][k], Q|K only
__device__ __half g_Wtl[2048 * D_IN];
__device__ __half g_Wvh[1024 * D_IN];   // V weights [n][k]
__device__ __half g_Wvl[1024 * D_IN];
__device__ __half g_Woth[D_IN * D_IN];  // [n][k] = Wo[k][n], hi only
__device__ __half g_ctxh[N_TOK * D_IN];

__device__ __forceinline__ void split_store(float v, __half* hi, __half* lo) {
    __half h = __float2half_rn(v);
    *hi = h;
    *lo = __float2half_rn(v - __half2float(h));
}

__device__ __forceinline__ uint32_t smem_u32(const void* p) {
    uint32_t a;
    asm("{ .reg .u64 t; cvta.to.shared.u64 t, %1; cvt.u32.u64 %0, t; }" : "=r"(a) : "l"(p));
    return a;
}
__device__ __forceinline__ void cp16(uint32_t dst, const void* src) {
    asm volatile("cp.async.cg.shared.global [%0], [%1], 16;" :: "r"(dst), "l"(src) : "memory");
}
#define CP_COMMIT() asm volatile("cp.async.commit_group;" ::: "memory")
#define CP_WAIT0()  asm volatile("cp.async.wait_group 0;" ::: "memory")
#define CP_WAIT1()  asm volatile("cp.async.wait_group 1;" ::: "memory")

__device__ __forceinline__ void mma_f(float* d, const uint32_t* a, const uint32_t* b) {
    asm volatile(
        "mma.sync.aligned.m16n8k16.row.col.f32.f16.f16.f32 "
        "{%0,%1,%2,%3}, {%4,%5,%6,%7}, {%8,%9}, {%0,%1,%2,%3};"
        : "+f"(d[0]), "+f"(d[1]), "+f"(d[2]), "+f"(d[3])
        : "r"(a[0]), "r"(a[1]), "r"(a[2]), "r"(a[3]), "r"(b[0]), "r"(b[1]));
}

__device__ __forceinline__ void ldsm_x4(uint32_t* r, uint32_t addr) {
    asm volatile("ldmatrix.sync.aligned.m8n8.x4.shared.b16 {%0,%1,%2,%3}, [%4];"
                 : "=r"(r[0]), "=r"(r[1]), "=r"(r[2]), "=r"(r[3]) : "r"(addr));
}

__device__ __forceinline__ uint32_t pack_h2(float p0, float p1) {
    __half2 h = __floats2half2_rn(p0, p1);
    return *(uint32_t*)&h;
}
__device__ __forceinline__ void split_pack(float p0, float p1, uint32_t& wh, uint32_t& wl) {
    wh = pack_h2(p0, p1);
    float2 f = __half22float2(*(__half2*)&wh);
    wl = pack_h2(p0 - f.x, p1 - f.y);
}

// e^x on the FFMA pipe
__device__ __forceinline__ float fast_exp(float x) {
    x = fmaxf(x, -80.f);
    float t = fmaf(x, 1.4426950408889634f, 12582912.f);
    int   i = __float_as_int(t);
    float r = t - 12582912.f;
    float f = fmaf(x, 1.4426950408889634f, -r);
    float p = 1.3333558e-3f;
    p = fmaf(p, f, 9.6181291e-3f);
    p = fmaf(p, f, 5.5504109e-2f);
    p = fmaf(p, f, 2.4022651e-1f);
    p = fmaf(p, f, 6.9314718e-1f);
    p = fmaf(p, f, 1.0f);
    return __int_as_float(__float_as_int(p) + (i << 23));
}

// ===========================================================================
// Prep kernels
// ===========================================================================
__global__ __launch_bounds__(256) void split_x_kernel(const float* __restrict__ x)
{
    int i0 = (blockIdx.x * 256 + threadIdx.x) * 4;
    float4 v = *(const float4*)(x + i0);
    split_store(v.x, &g_xh[i0 + 0], &g_xl[i0 + 0]);
    split_store(v.y, &g_xh[i0 + 1], &g_xl[i0 + 1]);
    split_store(v.z, &g_xh[i0 + 2], &g_xl[i0 + 2]);
    split_store(v.w, &g_xh[i0 + 3], &g_xl[i0 + 3]);
}

// Fused weight conversion: z<3 -> Wq/Wk/Wv, z==3 -> Wo.
__global__ __launch_bounds__(256) void conv_all_kernel(
    const float* __restrict__ Wq, const float* __restrict__ Wk,
    const float* __restrict__ Wv, const float* __restrict__ Wo)
{
    __shared__ float t[64][65];
    const int tid = threadIdx.x;
    const int sel = blockIdx.z;

    if (sel < 3) {
        const int d0 = blockIdx.x * 64, h = blockIdx.y;
        const float* W = (sel == 0 ? Wq : (sel == 1 ? Wk : Wv)) + (size_t)h * (D_IN * E);
        #pragma unroll
        for (int i = 0; i < 16; i++) {
            int idx = i * 256 + tid, r = idx >> 6, e = idx & 63;
            t[r][e] = W[(size_t)(d0 + r) * E + e];
        }
        __syncthreads();
        const int nb = h * 64;
        #pragma unroll
        for (int i = 0; i < 16; i++) {
            int idx = i * 256 + tid, er = idx >> 6, d = idx & 63;
            float v = t[d][er];
            if (sel < 2) {
                size_t o = (size_t)(sel * 1024 + nb + er) * D_IN + d0 + d;
                split_store(v, &g_Wth[o], &g_Wtl[o]);
            } else {
                size_t o = (size_t)(nb + er) * D_IN + d0 + d;
                split_store(v, &g_Wvh[o], &g_Wvl[o]);
            }
        }
    } else {
        const int k0 = blockIdx.x * 64, n0 = blockIdx.y * 64;
        #pragma unroll
        for (int i = 0; i < 16; i++) {
            int idx = i * 256 + tid, r = idx >> 6, c = idx & 63;
            t[r][c] = Wo[(size_t)(k0 + r) * D_IN + n0 + c];
        }
        __syncthreads();
        #pragma unroll
        for (int i = 0; i < 16; i++) {
            int idx = i * 256 + tid, nr = idx >> 6, k = idx & 63;
            g_Woth[(size_t)(n0 + nr) * D_IN + k0 + k] = __float2half_rn(t[k][nr]);
        }
    }
}

// ===========================================================================
// 3-term GEMM (QK): C = (A_h+A_l) @ (B_h+B_l)^T, drop lo*lo. BN=128.
// ===========================================================================
#define TSTRB 80
#define ATILE_B (128 * TSTRB)            // 10240

__global__ __launch_bounds__(256, 2) void gemm3_kernel(
    const __half* __restrict__ Ah, const __half* __restrict__ Al,
    const __half* __restrict__ Bh, const __half* __restrict__ Bl)
{
    constexpr int BN = 128;
    constexpr int BTILE_B = BN * TSTRB;
    constexpr int BUF_B   = 2 * ATILE_B + 2 * BTILE_B;
    constexpr int NP      = BN / 32;     // 4
    extern __shared__ __align__(16) char smem[];
    const int tid  = threadIdx.x;
    const int wid  = tid >> 5, lane = tid & 31;
    const int grp  = lane >> 2, qid = lane & 3;
    const int n0   = blockIdx.x * BN, m0 = blockIdx.y * 128;
    const int wm   = (wid >> 1) * 32;
    const int wn   = (wid & 1) * (BN / 2);

    const uint32_t smb = smem_u32(smem);

    const int arow  = ((lane >> 3) & 1) * 8 + (lane & 7);
    const int acol  = ((lane >> 4) & 1) * 16;
    const int brow  = ((lane >> 4) & 1) * 8 + (lane & 7);
    const int bcol  = ((lane >> 3) & 1) * 16;

    float acc[2][2 * NP][4] = {};

    auto load_tiles = [&](int buf, int kc) {
        const uint32_t bb = smb + buf * BUF_B;
        #pragma unroll
        for (int i = 0; i < 4; i++) {
            int c = i * 256 + tid;
            int t = c >> 9, w = c & 511, row = w >> 2, ch = w & 3;
            const __half* S = (t ? Al : Ah);
            cp16(bb + t * ATILE_B + row * TSTRB + ch * 16,
                 S + (size_t)(m0 + row) * D_IN + kc * 32 + ch * 8);
        }
        #pragma unroll
        for (int i = 0; i < 4; i++) {
            int c = i * 256 + tid;
            int t = c >> 9, w = c & 511, row = w >> 2, ch = w & 3;
            const __half* S = (t ? Bl : Bh);
            cp16(bb + 2 * ATILE_B + t * BTILE_B + row * TSTRB + ch * 16,
                 S + (size_t)(n0 + row) * D_IN + kc * 32 + ch * 8);
        }
    };

    load_tiles(0, 0);
    CP_COMMIT();

    const int NC = D_IN / 32;
    #pragma unroll 1
    for (int kc = 0; kc < NC; kc++) {
        const int cur = kc & 1;
        if (kc + 1 < NC) {
            load_tiles(1 - cur, kc + 1);
            CP_COMMIT();
            CP_WAIT1();
        } else {
            CP_WAIT0();
        }
        __syncthreads();

        const uint32_t Ah_b = smb + cur * BUF_B;
        const uint32_t Al_b = Ah_b + ATILE_B;
        const uint32_t Bh_b = Ah_b + 2 * ATILE_B;
        const uint32_t Bl_b = Bh_b + BTILE_B;

        #pragma unroll
        for (int k16 = 0; k16 < 2; k16++) {
            const int cb = k16 * 32 + acol;
            uint32_t ah0[4], ah1[4], al0[4], al1[4];
            ldsm_x4(ah0, Ah_b + (wm + arow) * TSTRB + cb);
            ldsm_x4(ah1, Ah_b + (wm + 16 + arow) * TSTRB + cb);
            ldsm_x4(al0, Al_b + (wm + arow) * TSTRB + cb);
            ldsm_x4(al1, Al_b + (wm + 16 + arow) * TSTRB + cb);
            const int cbb = k16 * 32 + bcol;
            #pragma unroll
            for (int np = 0; np < NP; np++) {
                uint32_t bh[4], bl[4];
                ldsm_x4(bh, Bh_b + (wn + np * 16 + brow) * TSTRB + cbb);
                ldsm_x4(bl, Bl_b + (wn + np * 16 + brow) * TSTRB + cbb);
                mma_f(acc[0][2*np],   ah0, bh);
                mma_f(acc[0][2*np+1], ah0, bh + 2);
                mma_f(acc[1][2*np],   ah1, bh);
                mma_f(acc[1][2*np+1], ah1, bh + 2);
                mma_f(acc[0][2*np],   ah0, bl);
                mma_f(acc[0][2*np+1], ah0, bl + 2);
                mma_f(acc[1][2*np],   ah1, bl);
                mma_f(acc[1][2*np+1], ah1, bl + 2);
                mma_f(acc[0][2*np],   al0, bh);
                mma_f(acc[0][2*np+1], al0, bh + 2);
                mma_f(acc[1][2*np],   al1, bh);
                mma_f(acc[1][2*np+1], al1, bh + 2);
            }
        }
        __syncthreads();
    }

    // epilogue: Q/K split
    #pragma unroll
    for (int mt = 0; mt < 2; mt++) {
        #pragma unroll
        for (int nt = 0; nt < 2 * NP; nt++) {
            int n = n0 + wn + nt * 8 + qid * 2;
            #pragma unroll
            for (int half = 0; half < 2; half++) {
                int m = m0 + wm + mt * 16 + grp + half * 8;
                float v0 = acc[mt][nt][half * 2], v1 = acc[mt][nt][half * 2 + 1];
                int sel = n >> 10, w = n & 1023, h = w >> 6, e = w & 63;
                __half* bh = (sel == 0 ? g_Qh : g_Kh);
                __half* bl = (sel == 0 ? g_Ql : g_Kl);
                size_t o = ((size_t)h * N_TOK + m) * E + e;
                uint32_t wh, wl;
                split_pack(v0, v1, wh, wl);
                *(uint32_t*)(bh + o) = wh;
                *(uint32_t*)(bl + o) = wl;
            }
        }
    }
}
#define GEMM3_SMEM (2 * (2 * ATILE_B + 2 * 128 * TSTRB))  // 81920

// ===========================================================================
// 2-term GEMM (V): V = x_h @ (Wv_h + Wv_l)^T. BN=64. Epilogue: Vt hi-only.
// ===========================================================================
__global__ __launch_bounds__(256, 2) void gemm2v_kernel(
    const __half* __restrict__ Ah,
    const __half* __restrict__ Bh, const __half* __restrict__ Bl)
{
    constexpr int BN = 64;
    constexpr int BTILE_B = BN * TSTRB;
    constexpr int BUF_B   = ATILE_B + 2 * BTILE_B;
    constexpr int NP      = BN / 32;     // 2
    extern __shared__ __align__(16) char smem[];
    const int tid  = threadIdx.x;
    const int wid  = tid >> 5, lane = tid & 31;
    const int grp  = lane >> 2, qid = lane & 3;
    const int n0   = blockIdx.x * BN, m0 = blockIdx.y * 128;
    const int wm   = (wid >> 1) * 32;
    const int wn   = (wid & 1) * (BN / 2);

    const uint32_t smb = smem_u32(smem);

    const int arow  = ((lane >> 3) & 1) * 8 + (lane & 7);
    const int acol  = ((lane >> 4) & 1) * 16;
    const int brow  = ((lane >> 4) & 1) * 8 + (lane & 7);
    const int bcol  = ((lane >> 3) & 1) * 16;

    float acc[2][2 * NP][4] = {};

    auto load_tiles = [&](int buf, int kc) {
        const uint32_t bb = smb + buf * BUF_B;
        #pragma unroll
        for (int i = 0; i < 2; i++) {
            int c = i * 256 + tid;
            int row = c >> 2, ch = c & 3;
            cp16(bb + row * TSTRB + ch * 16,
                 Ah + (size_t)(m0 + row) * D_IN + kc * 32 + ch * 8);
        }
        #pragma unroll
        for (int i = 0; i < 2; i++) {
            int c = i * 256 + tid;
            int t = c >> 8, w = c & 255, row = w >> 2, ch = w & 3;
            const __half* S = (t ? Bl : Bh);
            cp16(bb + ATILE_B + t * BTILE_B + row * TSTRB + ch * 16,
                 S + (size_t)(n0 + row) * D_IN + kc * 32 + ch * 8);
        }
    };

    load_tiles(0, 0);
    CP_COMMIT();

    const int NC = D_IN / 32;
    #pragma unroll 1
    for (int kc = 0; kc < NC; kc++) {
        const int cur = kc & 1;
        if (kc + 1 < NC) {
            load_tiles(1 - cur, kc + 1);
            CP_COMMIT();
            CP_WAIT1();
        } else {
            CP_WAIT0();
        }
        __syncthreads();

        const uint32_t A_b  = smb + cur * BUF_B;
        const uint32_t Bh_b = A_b + ATILE_B;
        const uint32_t Bl_b = Bh_b + BTILE_B;

        #pragma unroll
        for (int k16 = 0; k16 < 2; k16++) {
            const int cb = k16 * 32 + acol;
            uint32_t a0[4], a1[4];
            ldsm_x4(a0, A_b + (wm + arow) * TSTRB + cb);
            ldsm_x4(a1, A_b + (wm + 16 + arow) * TSTRB + cb);
            const int cbb = k16 * 32 + bcol;
            #pragma unroll
            for (int np = 0; np < NP; np++) {
                uint32_t bh[4], bl[4];
                ldsm_x4(bh, Bh_b + (wn + np * 16 + brow) * TSTRB + cbb);
                ldsm_x4(bl, Bl_b + (wn + np * 16 + brow) * TSTRB + cbb);
                mma_f(acc[0][2*np],   a0, bh);
                mma_f(acc[0][2*np+1], a0, bh + 2);
                mma_f(acc[1][2*np],   a1, bh);
                mma_f(acc[1][2*np+1], a1, bh + 2);
                mma_f(acc[0][2*np],   a0, bl);
                mma_f(acc[0][2*np+1], a0, bl + 2);
                mma_f(acc[1][2*np],   a1, bl);
                mma_f(acc[1][2*np+1], a1, bl + 2);
            }
        }
        __syncthreads();
    }

    // epilogue: Vt hi-only transposed [h][e][n]
    #pragma unroll
    for (int mt = 0; mt < 2; mt++) {
        #pragma unroll
        for (int nt = 0; nt < 2 * NP; nt++) {
            int n = n0 + wn + nt * 8 + qid * 2;
            int h = n >> 6, e = n & 63;
            #pragma unroll
            for (int half = 0; half < 2; half++) {
                int m = m0 + wm + mt * 16 + grp + half * 8;
                size_t o = ((size_t)h * E + e) * N_TOK + m;
                g_Vth[o]         = __float2half_rn(acc[mt][nt][half * 2]);
                g_Vth[o + N_TOK] = __float2half_rn(acc[mt][nt][half * 2 + 1]);
            }
        }
    }
}
#define GEMM2V_SMEM (2 * (ATILE_B + 2 * 64 * TSTRB))      // 40960

// ===========================================================================
// 1-term GEMM (outproj): out = ctx_h @ Wo_h^T, fp32 out. BN=64.
// ===========================================================================
__global__ __launch_bounds__(256, 2) void gemm1_kernel(
    const __half* __restrict__ Ah, const __half* __restrict__ Bh,
    float* __restrict__ outp)
{
    constexpr int BN = 64;
    constexpr int BTILE_B = BN * TSTRB;
    constexpr int BUF_B   = ATILE_B + BTILE_B;
    constexpr int NP      = BN / 32;     // 2
    extern __shared__ __align__(16) char smem[];
    const int tid  = threadIdx.x;
    const int wid  = tid >> 5, lane = tid & 31;
    const int grp  = lane >> 2, qid = lane & 3;
    const int n0   = blockIdx.x * BN, m0 = blockIdx.y * 128;
    const int wm   = (wid >> 1) * 32;
    const int wn   = (wid & 1) * (BN / 2);

    const uint32_t smb = smem_u32(smem);

    const int arow  = ((lane >> 3) & 1) * 8 + (lane & 7);
    const int acol  = ((lane >> 4) & 1) * 16;
    const int brow  = ((lane >> 4) & 1) * 8 + (lane & 7);
    const int bcol  = ((lane >> 3) & 1) * 16;

    float acc[2][2 * NP][4] = {};

    auto load_tiles = [&](int buf, int kc) {
        const uint32_t bb = smb + buf * BUF_B;
        #pragma unroll
        for (int i = 0; i < 2; i++) {
            int c = i * 256 + tid;
            int row = c >> 2, ch = c & 3;
            cp16(bb + row * TSTRB + ch * 16,
                 Ah + (size_t)(m0 + row) * D_IN + kc * 32 + ch * 8);
        }
        {
            int c = tid;
            int row = c >> 2, ch = c & 3;
            cp16(bb + ATILE_B + row * TSTRB + ch * 16,
                 Bh + (size_t)(n0 + row) * D_IN + kc * 32 + ch * 8);
        }
    };

    load_tiles(0, 0);
    CP_COMMIT();

    const int NC = D_IN / 32;
    #pragma unroll 1
    for (int kc = 0; kc < NC; kc++) {
        const int cur = kc & 1;
        if (kc + 1 < NC) {
            load_tiles(1 - cur, kc + 1);
            CP_COMMIT();
            CP_WAIT1();
        } else {
            CP_WAIT0();
        }
        __syncthreads();

        const uint32_t A_b  = smb + cur * BUF_B;
        const uint32_t Bh_b = A_b + ATILE_B;

        #pragma unroll
        for (int k16 = 0; k16 < 2; k16++) {
            const int cb = k16 * 32 + acol;
            uint32_t a0[4], a1[4];
            ldsm_x4(a0, A_b + (wm + arow) * TSTRB + cb);
            ldsm_x4(a1, A_b + (wm + 16 + arow) * TSTRB + cb);
            const int cbb = k16 * 32 + bcol;
            #pragma unroll
            for (int np = 0; np < NP; np++) {
                uint32_t bh[4];
                ldsm_x4(bh, Bh_b + (wn + np * 16 + brow) * TSTRB + cbb);
                mma_f(acc[0][2*np],   a0, bh);
                mma_f(acc[0][2*np+1], a0, bh + 2);
                mma_f(acc[1][2*np],   a1, bh);
                mma_f(acc[1][2*np+1], a1, bh + 2);
            }
        }
        __syncthreads();
    }

    #pragma unroll
    for (int mt = 0; mt < 2; mt++) {
        #pragma unroll
        for (int nt = 0; nt < 2 * NP; nt++) {
            int n = n0 + wn + nt * 8 + qid * 2;
            #pragma unroll
            for (int half = 0; half < 2; half++) {
                int m = m0 + wm + mt * 16 + grp + half * 8;
                *(float2*)(outp + (size_t)m * D_IN + n) =
                    make_float2(acc[mt][nt][half * 2], acc[mt][nt][half * 2 + 1]);
            }
        }
    }
}
#define GEMM1_SMEM (2 * (ATILE_B + 64 * TSTRB))           // 30720

// ===========================================================================
// HMMA flash attention. S: 3-term. PV: 1-term. ctx hi-only.
// ===========================================================================
#define BQ 128
#define BK 64
#define KSTR 144
#define VSTR 144
#define QBUF  (128 * KSTR)
#define OFF_Q   0
#define KBUF  (BK * KSTR)
#define OFF_K0  (2 * QBUF)
#define OFF_K1  (OFF_K0 + 2 * KBUF)
#define VBUF  (E * VSTR)
#define OFF_VT0 (OFF_K1 + 2 * KBUF)
#define OFF_VT1 (OFF_VT0 + VBUF)
#define ATTN_SMEM (OFF_VT1 + VBUF)           // 92160

__global__ __launch_bounds__(256, 2) void attn_kernel()
{
    extern __shared__ __align__(16) char smem[];
    const uint32_t smb = smem_u32(smem);
    const int tid = threadIdx.x, wid = tid >> 5, lane = tid & 31;
    const int grp = lane >> 2, qid = lane & 3;
    const int h = blockIdx.y;
    const int q0 = blockIdx.x * BQ;
    const int wm = wid * 16;

    const __half* gQh = g_Qh + ((size_t)h * N_TOK + q0) * E;
    const __half* gQl = g_Ql + ((size_t)h * N_TOK + q0) * E;
    const __half* gKh = g_Kh + (size_t)h * N_TOK * E;
    const __half* gKl = g_Kl + (size_t)h * N_TOK * E;
    const __half* gVth = g_Vth + (size_t)h * E * N_TOK;

    const int arow = ((lane >> 3) & 1) * 8 + (lane & 7);
    const int acol = ((lane >> 4) & 1) * 16;
    const int brow = ((lane >> 4) & 1) * 8 + (lane & 7);
    const int bcol = ((lane >> 3) & 1) * 16;

    auto load_kv = [&](uint32_t koff, uint32_t voff, int c) {
        #pragma unroll
        for (int i = 0; i < 4; i++) {
            int idx = i * 256 + tid;
            int t = idx >> 9, w = idx & 511, row = w >> 3, ch = w & 7;
            const __half* S = (t ? gKl : gKh);
            cp16(smb + koff + t * KBUF + row * KSTR + ch * 16,
                 S + ((size_t)c * BK + row) * E + ch * 8);
        }
        #pragma unroll
        for (int i = 0; i < 2; i++) {
            int idx = i * 256 + tid;
            int row = idx >> 3, ch = idx & 7;
            cp16(smb + voff + row * VSTR + ch * 16,
                 gVth + (size_t)row * N_TOK + c * BK + ch * 8);
        }
    };

    #pragma unroll
    for (int i = 0; i < 4; i++) {
        int idx = i * 256 + tid;
        int row = idx >> 3, ch = idx & 7;
        uint32_t so = row * KSTR + ch * 16;
        size_t  go = (size_t)row * E + ch * 8;
        cp16(smb + OFF_Q + so,        gQh + go);
        cp16(smb + OFF_Q + QBUF + so, gQl + go);
    }
    load_kv(OFF_K0, OFF_VT0, 0);
    CP_COMMIT();

    float accO[8][4] = {};
    float m0 = -1e30f, m1 = -1e30f, l0 = 0.f, l1 = 0.f;

    CP_WAIT0();
    __syncthreads();

    for (int c = 0; c < N_TOK / BK; c++) {
        const uint32_t kb  = smb + ((c & 1) ? OFF_K1 : OFF_K0);
        const uint32_t vtb = smb + ((c & 1) ? OFF_VT1 : OFF_VT0);

        float accS[8][4] = {};
        #pragma unroll
        for (int k16 = 0; k16 < 4; k16++) {
            uint32_t ah[4], al[4];
            const uint32_t aaddr = smb + OFF_Q + (wm + arow) * KSTR + k16 * 32 + acol;
            ldsm_x4(ah, aaddr);
            ldsm_x4(al, aaddr + QBUF);
            #pragma unroll
            for (int np = 0; np < 4; np++) {
                uint32_t bh[4], bl[4];
                const uint32_t baddr = kb + (np * 16 + brow) * KSTR + k16 * 32 + bcol;
                ldsm_x4(bh, baddr);
                ldsm_x4(bl, baddr + KBUF);
                mma_f(accS[2*np],   ah, bh);
                mma_f(accS[2*np+1], ah, bh + 2);
                mma_f(accS[2*np],   ah, bl);
                mma_f(accS[2*np+1], ah, bl + 2);
                mma_f(accS[2*np],   al, bh);
                mma_f(accS[2*np+1], al, bh + 2);
            }
        }

        if (c + 1 < N_TOK / BK) {
            load_kv((c & 1) ? OFF_K0 : OFF_K1, (c & 1) ? OFF_VT0 : OFF_VT1, c + 1);
            CP_COMMIT();
        }

        float mx0 = -1e30f, mx1 = -1e30f;
        #pragma unroll
        for (int n8 = 0; n8 < 8; n8++) {
            mx0 = fmaxf(mx0, fmaxf(accS[n8][0], accS[n8][1]));
            mx1 = fmaxf(mx1, fmaxf(accS[n8][2], accS[n8][3]));
        }
        mx0 = fmaxf(mx0, __shfl_xor_sync(0xffffffff, mx0, 1));
        mx0 = fmaxf(mx0, __shfl_xor_sync(0xffffffff, mx0, 2));
        mx1 = fmaxf(mx1, __shfl_xor_sync(0xffffffff, mx1, 1));
        mx1 = fmaxf(mx1, __shfl_xor_sync(0xffffffff, mx1, 2));
        float mn0 = fmaxf(m0, mx0), mn1 = fmaxf(m1, mx1);
        float al0 = fast_exp((m0 - mn0) * 0.125f);
        float al1 = fast_exp((m1 - mn1) * 0.125f);
        m0 = mn0; m1 = mn1;
        float s0 = 0.f, s1 = 0.f;
        #pragma unroll
        for (int n8 = 0; n8 < 8; n8++) {
            accS[n8][0] = fast_exp((accS[n8][0] - m0) * 0.125f);
            accS[n8][1] = fast_exp((accS[n8][1] - m0) * 0.125f);
            accS[n8][2] = fast_exp((accS[n8][2] - m1) * 0.125f);
            accS[n8][3] = fast_exp((accS[n8][3] - m1) * 0.125f);
            s0 += accS[n8][0] + accS[n8][1];
            s1 += accS[n8][2] + accS[n8][3];
        }
        s0 += __shfl_xor_sync(0xffffffff, s0, 1);
        s0 += __shfl_xor_sync(0xffffffff, s0, 2);
        s1 += __shfl_xor_sync(0xffffffff, s1, 1);
        s1 += __shfl_xor_sync(0xffffffff, s1, 2);
        l0 = l0 * al0 + s0;
        l1 = l1 * al1 + s1;
        #pragma unroll
        for (int n8v = 0; n8v < 8; n8v++) {
            accO[n8v][0] *= al0; accO[n8v][1] *= al0;
            accO[n8v][2] *= al1; accO[n8v][3] *= al1;
        }

        #pragma unroll
        for (int kk = 0; kk < 4; kk++) {
            uint32_t ph[4];
            ph[0] = pack_h2(accS[2 * kk][0],     accS[2 * kk][1]);
            ph[1] = pack_h2(accS[2 * kk][2],     accS[2 * kk][3]);
            ph[2] = pack_h2(accS[2 * kk + 1][0], accS[2 * kk + 1][1]);
            ph[3] = pack_h2(accS[2 * kk + 1][2], accS[2 * kk + 1][3]);
            #pragma unroll
            for (int np = 0; np < 4; np++) {
                uint32_t bh[4];
                ldsm_x4(bh, vtb + (np * 16 + brow) * VSTR + kk * 32 + bcol);
                mma_f(accO[2*np],   ph, bh);
                mma_f(accO[2*np+1], ph, bh + 2);
            }
        }

        if (c + 1 < N_TOK / BK) {
            CP_WAIT0();
            __syncthreads();
        }
    }

    float inv0 = 1.f / l0, inv1 = 1.f / l1;
    const int row0 = q0 + wm + grp, row1 = row0 + 8;
    #pragma unroll
    for (int n8v = 0; n8v < 8; n8v++) {
        int colb = h * E + n8v * 8 + qid * 2;
        *(uint32_t*)(g_ctxh + (size_t)row0 * D_IN + colb) =
            pack_h2(accO[n8v][0] * inv0, accO[n8v][1] * inv0);
        *(uint32_t*)(g_ctxh + (size_t)row1 * D_IN + colb) =
            pack_h2(accO[n8v][2] * inv1, accO[n8v][3] * inv1);
    }
}

// ===========================================================================
extern "C" void kernel_launch(void* const* d_in, const int* in_sizes, int n_in,
                              void* d_out, int out_size)
{
    const float* x  = (const float*)d_in[0];
    const float* Wq = (const float*)d_in[1];
    const float* Wk = (const float*)d_in[2];
    const float* Wv = (const float*)d_in[3];
    const float* Wo = (const float*)d_in[4];
    float* out = (float*)d_out;
    (void)in_sizes; (void)n_in; (void)out_size;

    cudaFuncSetAttribute(attn_kernel,
                         cudaFuncAttributeMaxDynamicSharedMemorySize, ATTN_SMEM);
    cudaFuncSetAttribute(gemm3_kernel,
                         cudaFuncAttributeMaxDynamicSharedMemorySize, GEMM3_SMEM);
    cudaFuncSetAttribute(gemm2v_kernel,
                         cudaFuncAttributeMaxDynamicSharedMemorySize, GEMM2V_SMEM);
    cudaFuncSetAttribute(gemm1_kernel,
                         cudaFuncAttributeMaxDynamicSharedMemorySize, GEMM1_SMEM);

    static __half *p_xh = nullptr, *p_xl, *p_Wth, *p_Wtl, *p_Wvh, *p_Wvl, *p_Woth, *p_ch;
    if (!p_xh) {
        cudaGetSymbolAddress((void**)&p_xh,  g_xh);
        cudaGetSymbolAddress((void**)&p_xl,  g_xl);
        cudaGetSymbolAddress((void**)&p_Wth, g_Wth);
        cudaGetSymbolAddress((void**)&p_Wtl, g_Wtl);
        cudaGetSymbolAddress((void**)&p_Wvh, g_Wvh);
        cudaGetSymbolAddress((void**)&p_Wvl, g_Wvl);
        cudaGetSymbolAddress((void**)&p_Woth, g_Woth);
        cudaGetSymbolAddress((void**)&p_ch,  g_ctxh);
    }

    // prep (2 launches: split x, fused weight conversion)
    split_x_kernel<<<(N_TOK * D_IN) / (256 * 4), 256>>>(x);
    dim3 gc(D_IN / 64, 16, 4);
    conv_all_kernel<<<gc, 256>>>(Wq, Wk, Wv, Wo);

    // QK 3-term (BN=128: grid 16 x 16, single wave)
    dim3 g1(2048 / 128, N_TOK / 128);
    gemm3_kernel<<<g1, 256, GEMM3_SMEM>>>(p_xh, p_xl, p_Wth, p_Wtl);

    // V 2-term (BN=64: grid 16 x 16)
    dim3 gv(1024 / 64, N_TOK / 128);
    gemm2v_kernel<<<gv, 256, GEMM2V_SMEM>>>(p_xh, p_Wvh, p_Wvl);

    // HMMA flash attention
    dim3 g2(N_TOK / BQ, NH);
    attn_kernel<<<g2, 256, ATTN_SMEM>>>();

    // outproj 1-term (BN=64: grid 16 x 16)
    dim3 g3(D_IN / 64, N_TOK / 128);
    gemm1_kernel<<<g3, 256, GEMM1_SMEM>>>(p_ch, p_Woth, out);
}